// round 8
// baseline (speedup 1.0000x reference)
#include <cuda_runtime.h>
#include <math.h>

#define BB 8
#define TT 2048
#define SS 3
#define HH 12
#define WW 6
#define LL 512
#define NC 48
#define NN 4
#define RR 4
#define NTAP 9

typedef unsigned long long ull;

__device__ __forceinline__ ull ffma2(ull a, ull b, ull c) {
    ull d;
    asm("fma.rn.f32x2 %0, %1, %2, %3;" : "=l"(d) : "l"(a), "l"(b), "l"(c));
    return d;
}

// ---------------- device globals ----------
__device__ float g_envmean[BB][SS * HH];
__device__ float g_w[BB][NN][NTAP];

// ---------------- stats prepass --------------------------------------------
#define SROWS 21
__global__ __launch_bounds__(SROWS * NC) void stats_kernel(const float* __restrict__ x) {
    __shared__ float partial[SROWS][NC];
    int b = blockIdx.x;
    int tid = threadIdx.x;            // 0..1007
    int c = tid % NC;
    int r = tid / NC;                 // 0..20
    float s = 0.f;
    const float* xb = x + (size_t)b * TT * NC;
    for (int t = r; t < TT; t += SROWS) s += xb[(size_t)t * NC + c];
    partial[r][c] = s;
    __syncthreads();
    if (tid < NC) {
        float tot = 0.f;
#pragma unroll
        for (int k = 0; k < SROWS; k++) tot += partial[k][tid];
        float mean = tot * (1.0f / TT);
        if (tid < SS * HH) {
            g_envmean[b][tid] = mean;
        } else {
            int rem = tid - SS * HH;
            if (rem % 3 == 2) {
                int i = rem / 3;
                float sigma = fmaxf(mean, 0.001f);
                float inv2s2 = 0.5f / (sigma * sigma);
                float ws[NTAP];
                float wsum = 0.f;
#pragma unroll
                for (int j = 0; j < NTAP; j++) {
                    float k = (float)(j - RR);
                    ws[j] = expf(-k * k * inv2s2);
                    wsum += ws[j];
                }
                float inv = 1.0f / wsum;
#pragma unroll
                for (int j = 0; j < NTAP; j++) g_w[b][i][j] = ws[j] * inv;
            }
        }
    }
}

// ---------------- fused main kernel ----------------------------------------
#define LCHUNK 64          // floats along l per block (float2 per thread)
#define TTILE 8
#define TCHUNK 32
#define TSPAN 512
#define LATS_BLOCKS 768    // 8 lc * 4 tg * 24 bs

// noise: one item = one float4 column x 8 consecutive t
#define NQ_C0 8192
#define NQ_C1 40960
#define NQ_C2 172032
#define NQ_C3 696320
#define NOISE_BLOCKS ((NQ_C3 + 191) / 192)   // 3627

__device__ __forceinline__ void lats_body(
    const float* __restrict__ x,
    const float* __restrict__ LT,
    float* __restrict__ out)
{
    __shared__ float2 s_env2[2][HH][TCHUNK];       // double-buffered, pairs {e,e}

    const int bl = blockIdx.x;
    const int lc = bl & 7;            // 0..7
    const int tg = (bl >> 3) & 3;     // 0..3
    const int bs = bl >> 5;           // 0..23
    const int b  = bs / SS;
    const int s  = bs % SS;
    const int tid = threadIdx.x;
    const int w  = tid / 32;
    const int l2 = tid % 32;          // float2 index within 64-float chunk

    // This thread's 12 lat float2 values live in registers for the whole block
    ull lat[HH];
#pragma unroll
    for (int h = 0; h < HH; h++) {
        size_t gidx = (((size_t)(s * HH + h)) * (SS * WW) + (s * WW + w)) * LL
                      + (size_t)lc * LCHUNK + l2 * 2;
        union { float2 f; ull u; } lv;
        lv.f = __ldg((const float2*)&LT[gidx]);
        lat[h] = lv.u;
    }

    const float* em = &g_envmean[b][s * HH];
    const int e0h = tid / TCHUNK, e0t = tid % TCHUNK;
    const int e1h = (tid + 192) / TCHUNK, e1t = (tid + 192) % TCHUNK;
    const float em0 = em[e0h];
    const float em1 = em[e1h];

    const int tbase0 = tg * TSPAN;
    const float* xe0 = x + (size_t)(b * TT) * NC + s * HH;

    // prefetch chunk 0 env values into registers
    float v0 = xe0[(size_t)(tbase0 + e0t) * NC + e0h] - em0;
    float v1 = xe0[(size_t)(tbase0 + e1t) * NC + e1h] - em1;

    for (int tc = 0; tc < TSPAN / TCHUNK; ++tc) {
        const int p = tc & 1;
        s_env2[p][e0h][e0t] = make_float2(v0, v0);
        s_env2[p][e1h][e1t] = make_float2(v1, v1);
        if (tc + 1 < TSPAN / TCHUNK) {
            const int tbn = tbase0 + (tc + 1) * TCHUNK;
            v0 = xe0[(size_t)(tbn + e0t) * NC + e0h] - em0;
            v1 = xe0[(size_t)(tbn + e1t) * NC + e1h] - em1;
        }
        __syncthreads();

        const int tb = tbase0 + tc * TCHUNK;
#pragma unroll
        for (int sub = 0; sub < TCHUNK / TTILE; ++sub) {
            ull acc[TTILE];
#pragma unroll
            for (int t = 0; t < TTILE; t++) acc[t] = 0ull;

#pragma unroll
            for (int h = 0; h < HH; h++) {
                const ull lh = lat[h];
#pragma unroll
                for (int k = 0; k < TTILE / 2; k++) {
                    // one LDS.128 broadcast = env pairs for t = 2k, 2k+1
                    union { float4 f; ull u[2]; } ep;
                    ep.f = *(const float4*)&s_env2[p][h][sub * TTILE + 2 * k];
                    acc[2*k]   = ffma2(ep.u[0], lh, acc[2*k]);
                    acc[2*k+1] = ffma2(ep.u[1], lh, acc[2*k+1]);
                }
            }

            const int t0 = tb + sub * TTILE;
#pragma unroll
            for (int t = 0; t < TTILE; t++) {
                size_t o = (((size_t)(b * TT + t0 + t)) * (SS * WW) + (s * WW + w)) * LL
                           + (size_t)lc * LCHUNK + l2 * 2;
                union { float2 f; ull u; } r;
                r.u = acc[t];
                __stcs((float2*)&out[o], r.f);
            }
        }
    }
}

__device__ __forceinline__ int refl(int i) {
    i = (i < 0) ? -i : i;
    return (i >= TT) ? (2 * TT - 2 - i) : i;
}

// One noise item = one float4 column for 8 consecutive t (sliding window).
template<int P, int NI>
__device__ __forceinline__ void noise_body(
    int q,
    const float* __restrict__ x,
    const float* __restrict__ eps,
    float* __restrict__ out)
{
    constexpr int G4 = P / 4;
    const int g  = q % G4;
    const int tg = (q / G4) % (TT / 8);
    const int b  = q / (G4 * (TT / 8));
    const int t0 = tg * 8;

    float wl[NTAP];
    {
        const float* wr = g_w[b][NI];
#pragma unroll
        for (int j = 0; j < NTAP; j++) wl[j] = wr[j];
    }
    const float* xb = x + (size_t)b * TT * NC + SS * HH + 3 * NI;
    const float* eb = eps + (size_t)b * TT * P + g * 4;
    float* ob = out + ((size_t)b * TT + t0) * P + g * 4;

    float4 win[NTAP];
#pragma unroll
    for (int j = 0; j < NTAP; j++) {
        int idx = refl(t0 - RR + j);
        float mu = xb[(size_t)idx * NC];
        float sg = xb[(size_t)idx * NC + 1];
        float4 e = *(const float4*)&eb[(size_t)idx * P];
        win[j] = make_float4(fmaf(sg, e.x, mu), fmaf(sg, e.y, mu),
                             fmaf(sg, e.z, mu), fmaf(sg, e.w, mu));
    }

#pragma unroll
    for (int k = 0; k < 8; k++) {
        float4 a = make_float4(0.f, 0.f, 0.f, 0.f);
#pragma unroll
        for (int j = 0; j < NTAP; j++) {
            float4 v = win[(j + k) % NTAP];
            float wj = wl[j];
            a.x = fmaf(wj, v.x, a.x);
            a.y = fmaf(wj, v.y, a.y);
            a.z = fmaf(wj, v.z, a.z);
            a.w = fmaf(wj, v.w, a.w);
        }
        __stcs((float4*)&ob[(size_t)k * P], a);
        if (k < 7) {
            int idx = refl(t0 + k + RR + 1);
            float mu = xb[(size_t)idx * NC];
            float sg = xb[(size_t)idx * NC + 1];
            float4 e = *(const float4*)&eb[(size_t)idx * P];
            win[k % NTAP] = make_float4(fmaf(sg, e.x, mu), fmaf(sg, e.y, mu),
                                        fmaf(sg, e.z, mu), fmaf(sg, e.w, mu));
        }
    }
}

__global__ __launch_bounds__(192, 4) void main_kernel(
    const float* __restrict__ x,
    const float* __restrict__ LT,
    const float* __restrict__ e0,
    const float* __restrict__ e1,
    const float* __restrict__ e2,
    const float* __restrict__ e3,
    float* __restrict__ out)
{
    const size_t LATS = (size_t)BB * TT * (SS * WW) * LL;
    const size_t N0   = (size_t)BB * TT * 16;
    const size_t N1   = (size_t)BB * TT * 64;
    const size_t N2   = (size_t)BB * TT * 256;

    if (blockIdx.x < LATS_BLOCKS) {
        lats_body(x, LT, out);
    } else {
        int q = (blockIdx.x - LATS_BLOCKS) * 192 + threadIdx.x;
        if (q < NQ_C0) {
            noise_body<16, 0>(q, x, e0, out + LATS);
        } else if (q < NQ_C1) {
            noise_body<64, 1>(q - NQ_C0, x, e1, out + LATS + N0);
        } else if (q < NQ_C2) {
            noise_body<256, 2>(q - NQ_C1, x, e2, out + LATS + N0 + N1);
        } else if (q < NQ_C3) {
            noise_body<1024, 3>(q - NQ_C2, x, e3, out + LATS + N0 + N1 + N2);
        }
    }
}

// ---------------- launch ----------------------------------------------------
extern "C" void kernel_launch(void* const* d_in, const int* in_sizes, int n_in,
                              void* d_out, int out_size) {
    const float* x  = (const float*)d_in[0];
    const float* LT = (const float*)d_in[1];
    const float* e0 = (const float*)d_in[2];
    const float* e1 = (const float*)d_in[3];
    const float* e2 = (const float*)d_in[4];
    const float* e3 = (const float*)d_in[5];
    float* out = (float*)d_out;

    stats_kernel<<<BB, SROWS * NC>>>(x);
    main_kernel<<<LATS_BLOCKS + NOISE_BLOCKS, 192>>>(x, LT, e0, e1, e2, e3, out);
}

// round 9
// speedup vs baseline: 1.1843x; 1.1843x over previous
#include <cuda_runtime.h>
#include <math.h>

#define BB 8
#define TT 2048
#define SS 3
#define HH 12
#define WW 6
#define LL 512
#define NC 48
#define NN 4
#define RR 4
#define NTAP 9

typedef unsigned long long ull;

__device__ __forceinline__ ull ffma2(ull a, ull b, ull c) {
    ull d;
    asm("fma.rn.f32x2 %0, %1, %2, %3;" : "=l"(d) : "l"(a), "l"(b), "l"(c));
    return d;
}

// ---------------- device globals ----------
__device__ float g_envmean[BB][SS * HH];
__device__ float g_w[BB][NN][NTAP];

// ---------------- stats prepass --------------------------------------------
#define SROWS 21
__global__ __launch_bounds__(SROWS * NC) void stats_kernel(const float* __restrict__ x) {
    __shared__ float partial[SROWS][NC];
    int b = blockIdx.x;
    int tid = threadIdx.x;            // 0..1007
    int c = tid % NC;
    int r = tid / NC;                 // 0..20
    float s = 0.f;
    const float* xb = x + (size_t)b * TT * NC;
    for (int t = r; t < TT; t += SROWS) s += xb[(size_t)t * NC + c];
    partial[r][c] = s;
    __syncthreads();
    if (tid < NC) {
        float tot = 0.f;
#pragma unroll
        for (int k = 0; k < SROWS; k++) tot += partial[k][tid];
        float mean = tot * (1.0f / TT);
        if (tid < SS * HH) {
            g_envmean[b][tid] = mean;
        } else {
            int rem = tid - SS * HH;
            if (rem % 3 == 2) {
                int i = rem / 3;
                float sigma = fmaxf(mean, 0.001f);
                float inv2s2 = 0.5f / (sigma * sigma);
                float ws[NTAP];
                float wsum = 0.f;
#pragma unroll
                for (int j = 0; j < NTAP; j++) {
                    float k = (float)(j - RR);
                    ws[j] = expf(-k * k * inv2s2);
                    wsum += ws[j];
                }
                float inv = 1.0f / wsum;
#pragma unroll
                for (int j = 0; j < NTAP; j++) g_w[b][i][j] = ws[j] * inv;
            }
        }
    }
    __threadfence();
#if __CUDA_ARCH__ >= 900
    cudaTriggerProgrammaticLaunchCompletion();
#endif
}

// ---------------- fused main kernel ----------------------------------------
#define LCHUNK 128
#define TTILE 8
#define TCHUNK 32
#define TSPAN 512
#define LATS_BLOCKS 384    // 4 lc * 4 tg * 24 bs

// noise: one item = one float4 column x 8 consecutive t
#define NQ_C0 8192
#define NQ_C1 40960
#define NQ_C2 172032
#define NQ_C3 696320
#define NOISE_BLOCKS ((NQ_C3 + 191) / 192)   // 3627

__device__ __forceinline__ void pdl_wait() {
#if __CUDA_ARCH__ >= 900
    cudaGridDependencySynchronize();
#endif
}

__device__ __forceinline__ void lats_body(
    const float* __restrict__ x,
    const float* __restrict__ LT,
    float* __restrict__ out)
{
    __shared__ float2 s_env2[2][HH][TCHUNK];       // double-buffered, pairs {e,e}

    const int bl = blockIdx.x;
    const int lc = bl & 3;            // 0..3
    const int tg = (bl >> 2) & 3;     // 0..3
    const int bs = bl >> 4;           // 0..23
    const int b  = bs / SS;
    const int s  = bs % SS;
    const int tid = threadIdx.x;
    const int w  = tid / 32;
    const int l4 = tid % 32;

    // stats-independent prologue: this thread's 12 lat float4 values
    ull lat[HH][2];
#pragma unroll
    for (int h = 0; h < HH; h++) {
        size_t gidx = (((size_t)(s * HH + h)) * (SS * WW) + (s * WW + w)) * LL
                      + (size_t)lc * LCHUNK + l4 * 4;
        union { float4 f; ull u[2]; } lv;
        lv.f = __ldg((const float4*)&LT[gidx]);
        lat[h][0] = lv.u[0];
        lat[h][1] = lv.u[1];
    }

    pdl_wait();   // stats results needed from here on

    const float* em = &g_envmean[b][s * HH];
    const int e0h = tid / TCHUNK, e0t = tid % TCHUNK;
    const int e1h = (tid + 192) / TCHUNK, e1t = (tid + 192) % TCHUNK;
    const float em0 = em[e0h];
    const float em1 = em[e1h];

    const int tbase0 = tg * TSPAN;
    const float* xe0 = x + (size_t)(b * TT) * NC + s * HH;

    // prefetch chunk 0 env values into registers
    float v0 = xe0[(size_t)(tbase0 + e0t) * NC + e0h] - em0;
    float v1 = xe0[(size_t)(tbase0 + e1t) * NC + e1h] - em1;

    for (int tc = 0; tc < TSPAN / TCHUNK; ++tc) {
        const int p = tc & 1;
        s_env2[p][e0h][e0t] = make_float2(v0, v0);
        s_env2[p][e1h][e1t] = make_float2(v1, v1);
        if (tc + 1 < TSPAN / TCHUNK) {
            const int tbn = tbase0 + (tc + 1) * TCHUNK;
            v0 = xe0[(size_t)(tbn + e0t) * NC + e0h] - em0;
            v1 = xe0[(size_t)(tbn + e1t) * NC + e1h] - em1;
        }
        __syncthreads();

        const int tb = tbase0 + tc * TCHUNK;
#pragma unroll
        for (int sub = 0; sub < TCHUNK / TTILE; ++sub) {
            ull acc[TTILE][2];
#pragma unroll
            for (int t = 0; t < TTILE; t++) { acc[t][0] = 0ull; acc[t][1] = 0ull; }

#pragma unroll
            for (int h = 0; h < HH; h++) {
#pragma unroll
                for (int k = 0; k < TTILE / 2; k++) {
                    union { float4 f; ull u[2]; } ep;
                    ep.f = *(const float4*)&s_env2[p][h][sub * TTILE + 2 * k];
                    acc[2*k][0]   = ffma2(ep.u[0], lat[h][0], acc[2*k][0]);
                    acc[2*k][1]   = ffma2(ep.u[0], lat[h][1], acc[2*k][1]);
                    acc[2*k+1][0] = ffma2(ep.u[1], lat[h][0], acc[2*k+1][0]);
                    acc[2*k+1][1] = ffma2(ep.u[1], lat[h][1], acc[2*k+1][1]);
                }
            }

            const int t0 = tb + sub * TTILE;
#pragma unroll
            for (int t = 0; t < TTILE; t++) {
                size_t o = (((size_t)(b * TT + t0 + t)) * (SS * WW) + (s * WW + w)) * LL
                           + (size_t)lc * LCHUNK + l4 * 4;
                union { float4 f; ull u[2]; } r;
                r.u[0] = acc[t][0];
                r.u[1] = acc[t][1];
                __stcs((float4*)&out[o], r.f);
            }
        }
    }
}

__device__ __forceinline__ int refl(int i) {
    i = (i < 0) ? -i : i;
    return (i >= TT) ? (2 * TT - 2 - i) : i;
}

// One noise item = one float4 column for 8 consecutive t (sliding window).
template<int P, int NI>
__device__ __forceinline__ void noise_body(
    int q,
    const float* __restrict__ x,
    const float* __restrict__ eps,
    float* __restrict__ out)
{
    constexpr int G4 = P / 4;
    const int g  = q % G4;
    const int tg = (q / G4) % (TT / 8);
    const int b  = q / (G4 * (TT / 8));
    const int t0 = tg * 8;

    float wl[NTAP];
    {
        const float* wr = g_w[b][NI];
#pragma unroll
        for (int j = 0; j < NTAP; j++) wl[j] = wr[j];
    }
    const float* xb = x + (size_t)b * TT * NC + SS * HH + 3 * NI;
    const float* eb = eps + (size_t)b * TT * P + g * 4;
    float* ob = out + ((size_t)b * TT + t0) * P + g * 4;

    float4 win[NTAP];
#pragma unroll
    for (int j = 0; j < NTAP; j++) {
        int idx = refl(t0 - RR + j);
        float mu = xb[(size_t)idx * NC];
        float sg = xb[(size_t)idx * NC + 1];
        float4 e = *(const float4*)&eb[(size_t)idx * P];
        win[j] = make_float4(fmaf(sg, e.x, mu), fmaf(sg, e.y, mu),
                             fmaf(sg, e.z, mu), fmaf(sg, e.w, mu));
    }

#pragma unroll
    for (int k = 0; k < 8; k++) {
        float4 a = make_float4(0.f, 0.f, 0.f, 0.f);
#pragma unroll
        for (int j = 0; j < NTAP; j++) {
            float4 v = win[(j + k) % NTAP];
            float wj = wl[j];
            a.x = fmaf(wj, v.x, a.x);
            a.y = fmaf(wj, v.y, a.y);
            a.z = fmaf(wj, v.z, a.z);
            a.w = fmaf(wj, v.w, a.w);
        }
        __stcs((float4*)&ob[(size_t)k * P], a);
        if (k < 7) {
            int idx = refl(t0 + k + RR + 1);
            float mu = xb[(size_t)idx * NC];
            float sg = xb[(size_t)idx * NC + 1];
            float4 e = *(const float4*)&eb[(size_t)idx * P];
            win[k % NTAP] = make_float4(fmaf(sg, e.x, mu), fmaf(sg, e.y, mu),
                                        fmaf(sg, e.z, mu), fmaf(sg, e.w, mu));
        }
    }
}

__global__ __launch_bounds__(192, 3) void main_kernel(
    const float* __restrict__ x,
    const float* __restrict__ LT,
    const float* __restrict__ e0,
    const float* __restrict__ e1,
    const float* __restrict__ e2,
    const float* __restrict__ e3,
    float* __restrict__ out)
{
    const size_t LATS = (size_t)BB * TT * (SS * WW) * LL;
    const size_t N0   = (size_t)BB * TT * 16;
    const size_t N1   = (size_t)BB * TT * 64;
    const size_t N2   = (size_t)BB * TT * 256;

    if (blockIdx.x < LATS_BLOCKS) {
        lats_body(x, LT, out);
    } else {
        int q = (blockIdx.x - LATS_BLOCKS) * 192 + threadIdx.x;
        pdl_wait();   // noise path needs g_w
        if (q < NQ_C0) {
            noise_body<16, 0>(q, x, e0, out + LATS);
        } else if (q < NQ_C1) {
            noise_body<64, 1>(q - NQ_C0, x, e1, out + LATS + N0);
        } else if (q < NQ_C2) {
            noise_body<256, 2>(q - NQ_C1, x, e2, out + LATS + N0 + N1);
        } else if (q < NQ_C3) {
            noise_body<1024, 3>(q - NQ_C2, x, e3, out + LATS + N0 + N1 + N2);
        }
    }
}

// ---------------- launch ----------------------------------------------------
extern "C" void kernel_launch(void* const* d_in, const int* in_sizes, int n_in,
                              void* d_out, int out_size) {
    const float* x  = (const float*)d_in[0];
    const float* LT = (const float*)d_in[1];
    const float* e0 = (const float*)d_in[2];
    const float* e1 = (const float*)d_in[3];
    const float* e2 = (const float*)d_in[4];
    const float* e3 = (const float*)d_in[5];
    float* out = (float*)d_out;

    stats_kernel<<<BB, SROWS * NC>>>(x);

    // PDL: main starts while stats runs; device-side gridDependencySynchronize
    // gates the g_envmean / g_w consumers.
    cudaLaunchConfig_t cfg = {};
    cfg.gridDim  = dim3(LATS_BLOCKS + NOISE_BLOCKS, 1, 1);
    cfg.blockDim = dim3(192, 1, 1);
    cfg.dynamicSmemBytes = 0;
    cudaLaunchAttribute attrs[1];
    attrs[0].id = cudaLaunchAttributeProgrammaticStreamSerialization;
    attrs[0].val.programmaticStreamSerializationAllowed = 1;
    cfg.attrs = attrs;
    cfg.numAttrs = 1;
    cudaLaunchKernelEx(&cfg, main_kernel, x, LT, e0, e1, e2, e3, out);
}

// round 10
// speedup vs baseline: 1.2636x; 1.0670x over previous
#include <cuda_runtime.h>
#include <math.h>

#define BB 8
#define TT 2048
#define SS 3
#define HH 12
#define WW 6
#define LL 512
#define NC 48
#define NN 4
#define RR 4
#define NTAP 9
#define NPART 16

typedef unsigned long long ull;

__device__ __forceinline__ ull ffma2(ull a, ull b, ull c) {
    ull d;
    asm("fma.rn.f32x2 %0, %1, %2, %3;" : "=l"(d) : "l"(a), "l"(b), "l"(c));
    return d;
}

// ---------------- device globals ----------
// Per-slice column sums of x; fully overwritten every call (no zeroing needed).
__device__ float g_part[NPART][BB][NC];

// ---------------- stats partial kernel --------------------------------------
// grid = BB*NPART blocks; block = 384. Each block sums 128 t-rows x 48 channels.
__global__ __launch_bounds__(384) void stats_partial(const float* __restrict__ x) {
    __shared__ float partial[8][NC];
    const int blk = blockIdx.x;
    const int b  = blk / NPART;
    const int sl = blk % NPART;
    const int tid = threadIdx.x;      // 0..383
    const int c = tid % NC;
    const int r = tid / NC;           // 0..7
    const float* xb = x + ((size_t)b * TT + sl * (TT / NPART)) * NC;
    float s = 0.f;
#pragma unroll
    for (int t = r; t < TT / NPART; t += 8) s += xb[(size_t)t * NC + c];
    partial[r][c] = s;
    __syncthreads();
    if (tid < NC) {
        float tot = 0.f;
#pragma unroll
        for (int k = 0; k < 8; k++) tot += partial[k][tid];
        g_part[sl][b][tid] = tot;
    }
}

__device__ __forceinline__ float chan_mean(int b, int c) {
    float s = 0.f;
#pragma unroll
    for (int k = 0; k < NPART; k++) s += g_part[k][b][c];
    return s * (1.0f / TT);
}

// ---------------- fused main kernel ----------------------------------------
#define LCHUNK 128
#define TTILE 8
#define TCHUNK 32
#define TSPAN 512
#define LATS_BLOCKS 384    // 4 lc * 4 tg * 24 bs

// noise: one item = one float4 column x 8 consecutive t
#define NQ_C0 8192
#define NQ_C1 40960
#define NQ_C2 172032
#define NQ_C3 696320
#define NOISE_BLOCKS ((NQ_C3 + 191) / 192)   // 3627

__device__ __forceinline__ void lats_body(
    const float* __restrict__ x,
    const float* __restrict__ LT,
    float* __restrict__ out)
{
    __shared__ float2 s_env2[2][HH][TCHUNK];       // double-buffered, pairs {e,e}

    const int bl = blockIdx.x;
    const int lc = bl & 3;            // 0..3
    const int tg = (bl >> 2) & 3;     // 0..3
    const int bs = bl >> 4;           // 0..23
    const int b  = bs / SS;
    const int s  = bs % SS;
    const int tid = threadIdx.x;
    const int w  = tid / 32;
    const int l4 = tid % 32;

    // this thread's 12 lat float4 values (block-lifetime registers)
    ull lat[HH][2];
#pragma unroll
    for (int h = 0; h < HH; h++) {
        size_t gidx = (((size_t)(s * HH + h)) * (SS * WW) + (s * WW + w)) * LL
                      + (size_t)lc * LCHUNK + l4 * 4;
        union { float4 f; ull u[2]; } lv;
        lv.f = __ldg((const float4*)&LT[gidx]);
        lat[h][0] = lv.u[0];
        lat[h][1] = lv.u[1];
    }

    const int e0h = tid / TCHUNK, e0t = tid % TCHUNK;
    const int e1h = (tid + 192) / TCHUNK, e1t = (tid + 192) % TCHUNK;
    // finalize the two channel means this thread needs (16 L2 loads each)
    const float em0 = chan_mean(b, s * HH + e0h);
    const float em1 = chan_mean(b, s * HH + e1h);

    const int tbase0 = tg * TSPAN;
    const float* xe0 = x + (size_t)(b * TT) * NC + s * HH;

    // prefetch chunk 0 env values into registers
    float v0 = xe0[(size_t)(tbase0 + e0t) * NC + e0h] - em0;
    float v1 = xe0[(size_t)(tbase0 + e1t) * NC + e1h] - em1;

    for (int tc = 0; tc < TSPAN / TCHUNK; ++tc) {
        const int p = tc & 1;
        s_env2[p][e0h][e0t] = make_float2(v0, v0);
        s_env2[p][e1h][e1t] = make_float2(v1, v1);
        if (tc + 1 < TSPAN / TCHUNK) {
            const int tbn = tbase0 + (tc + 1) * TCHUNK;
            v0 = xe0[(size_t)(tbn + e0t) * NC + e0h] - em0;
            v1 = xe0[(size_t)(tbn + e1t) * NC + e1h] - em1;
        }
        __syncthreads();

        const int tb = tbase0 + tc * TCHUNK;
#pragma unroll
        for (int sub = 0; sub < TCHUNK / TTILE; ++sub) {
            ull acc[TTILE][2];
#pragma unroll
            for (int t = 0; t < TTILE; t++) { acc[t][0] = 0ull; acc[t][1] = 0ull; }

#pragma unroll
            for (int h = 0; h < HH; h++) {
#pragma unroll
                for (int k = 0; k < TTILE / 2; k++) {
                    union { float4 f; ull u[2]; } ep;
                    ep.f = *(const float4*)&s_env2[p][h][sub * TTILE + 2 * k];
                    acc[2*k][0]   = ffma2(ep.u[0], lat[h][0], acc[2*k][0]);
                    acc[2*k][1]   = ffma2(ep.u[0], lat[h][1], acc[2*k][1]);
                    acc[2*k+1][0] = ffma2(ep.u[1], lat[h][0], acc[2*k+1][0]);
                    acc[2*k+1][1] = ffma2(ep.u[1], lat[h][1], acc[2*k+1][1]);
                }
            }

            const int t0 = tb + sub * TTILE;
#pragma unroll
            for (int t = 0; t < TTILE; t++) {
                size_t o = (((size_t)(b * TT + t0 + t)) * (SS * WW) + (s * WW + w)) * LL
                           + (size_t)lc * LCHUNK + l4 * 4;
                union { float4 f; ull u[2]; } r;
                r.u[0] = acc[t][0];
                r.u[1] = acc[t][1];
                __stcs((float4*)&out[o], r.f);
            }
        }
    }
}

__device__ __forceinline__ int refl(int i) {
    i = (i < 0) ? -i : i;
    return (i >= TT) ? (2 * TT - 2 - i) : i;
}

// One noise item = one float4 column for 8 consecutive t (sliding window).
template<int P, int NI>
__device__ __forceinline__ void noise_body(
    int q,
    const float* __restrict__ x,
    const float* __restrict__ eps,
    float* __restrict__ out)
{
    constexpr int G4 = P / 4;
    const int g  = q % G4;
    const int tg = (q / G4) % (TT / 8);
    const int b  = q / (G4 * (TT / 8));
    const int t0 = tg * 8;

    // per-thread weight finalize: mean of smooth channel -> 9 gaussian taps
    float wl[NTAP];
    {
        float sigma = fmaxf(chan_mean(b, SS * HH + 3 * NI + 2), 0.001f);
        float inv2s2 = 0.5f / (sigma * sigma);
        float wsum = 0.f;
#pragma unroll
        for (int j = 0; j < NTAP; j++) {
            float kk = (float)(j - RR);
            wl[j] = expf(-kk * kk * inv2s2);
            wsum += wl[j];
        }
        float inv = 1.0f / wsum;
#pragma unroll
        for (int j = 0; j < NTAP; j++) wl[j] *= inv;
    }

    const float* xb = x + (size_t)b * TT * NC + SS * HH + 3 * NI;
    const float* eb = eps + (size_t)b * TT * P + g * 4;
    float* ob = out + ((size_t)b * TT + t0) * P + g * 4;

    float4 win[NTAP];
#pragma unroll
    for (int j = 0; j < NTAP; j++) {
        int idx = refl(t0 - RR + j);
        float mu = xb[(size_t)idx * NC];
        float sg = xb[(size_t)idx * NC + 1];
        float4 e = *(const float4*)&eb[(size_t)idx * P];
        win[j] = make_float4(fmaf(sg, e.x, mu), fmaf(sg, e.y, mu),
                             fmaf(sg, e.z, mu), fmaf(sg, e.w, mu));
    }

#pragma unroll
    for (int k = 0; k < 8; k++) {
        float4 a = make_float4(0.f, 0.f, 0.f, 0.f);
#pragma unroll
        for (int j = 0; j < NTAP; j++) {
            float4 v = win[(j + k) % NTAP];
            float wj = wl[j];
            a.x = fmaf(wj, v.x, a.x);
            a.y = fmaf(wj, v.y, a.y);
            a.z = fmaf(wj, v.z, a.z);
            a.w = fmaf(wj, v.w, a.w);
        }
        __stcs((float4*)&ob[(size_t)k * P], a);
        if (k < 7) {
            int idx = refl(t0 + k + RR + 1);
            float mu = xb[(size_t)idx * NC];
            float sg = xb[(size_t)idx * NC + 1];
            float4 e = *(const float4*)&eb[(size_t)idx * P];
            win[k % NTAP] = make_float4(fmaf(sg, e.x, mu), fmaf(sg, e.y, mu),
                                        fmaf(sg, e.z, mu), fmaf(sg, e.w, mu));
        }
    }
}

__global__ __launch_bounds__(192, 3) void main_kernel(
    const float* __restrict__ x,
    const float* __restrict__ LT,
    const float* __restrict__ e0,
    const float* __restrict__ e1,
    const float* __restrict__ e2,
    const float* __restrict__ e3,
    float* __restrict__ out)
{
    const size_t LATS = (size_t)BB * TT * (SS * WW) * LL;
    const size_t N0   = (size_t)BB * TT * 16;
    const size_t N1   = (size_t)BB * TT * 64;
    const size_t N2   = (size_t)BB * TT * 256;

    if (blockIdx.x < LATS_BLOCKS) {
        lats_body(x, LT, out);
    } else {
        int q = (blockIdx.x - LATS_BLOCKS) * 192 + threadIdx.x;
        if (q < NQ_C0) {
            noise_body<16, 0>(q, x, e0, out + LATS);
        } else if (q < NQ_C1) {
            noise_body<64, 1>(q - NQ_C0, x, e1, out + LATS + N0);
        } else if (q < NQ_C2) {
            noise_body<256, 2>(q - NQ_C1, x, e2, out + LATS + N0 + N1);
        } else if (q < NQ_C3) {
            noise_body<1024, 3>(q - NQ_C2, x, e3, out + LATS + N0 + N1 + N2);
        }
    }
}

// ---------------- launch ----------------------------------------------------
extern "C" void kernel_launch(void* const* d_in, const int* in_sizes, int n_in,
                              void* d_out, int out_size) {
    const float* x  = (const float*)d_in[0];
    const float* LT = (const float*)d_in[1];
    const float* e0 = (const float*)d_in[2];
    const float* e1 = (const float*)d_in[3];
    const float* e2 = (const float*)d_in[4];
    const float* e3 = (const float*)d_in[5];
    float* out = (float*)d_out;

    stats_partial<<<BB * NPART, 384>>>(x);
    main_kernel<<<LATS_BLOCKS + NOISE_BLOCKS, 192>>>(x, LT, e0, e1, e2, e3, out);
}